// round 16
// baseline (speedup 1.0000x reference)
#include <cuda_runtime.h>

// Problem constants (fixed by the reference: H=512, N=64, CH=1, L=2048)
#define HH   512
#define NST  64
#define LFFT 2048
#define NF   1024      // half-size complex IFFT length
#define NTH  256
#define LCHUNK 1024    // l-bins per chunk-block
#define NCHUNK (LFFT / LCHUNK)   // 2 blocks per head
#define JILP 4         // l-bins per thread

typedef unsigned long long ull;

// Scratch (static globals, no allocation):
__device__ float2 g_khat[HH * LFFT];        // 8 MB K_hat spectrum
__device__ unsigned int g_flag[HH];         // chunk0-done flags (memset each launch)

__device__ __forceinline__ ull pack2(float a, float b) {
    ull r;
    asm("mov.b64 %0, {%1, %2};" : "=l"(r) : "f"(a), "f"(b));
    return r;
}
__device__ __forceinline__ void unpack2(ull v, float& a, float& b) {
    asm("mov.b64 {%0, %1}, %2;" : "=f"(a), "=f"(b) : "l"(v));
}
__device__ __forceinline__ ull ffma2(ull a, ull b, ull c) {
    ull d;
    asm("fma.rn.f32x2 %0, %1, %2, %3;" : "=l"(d) : "l"(a), "l"(b), "l"(c));
    return d;
}
__device__ __forceinline__ ull fadd2(ull a, ull b) {
    ull d;
    asm("add.rn.f32x2 %0, %1, %2;" : "=l"(d) : "l"(a), "l"(b));
    return d;
}
__device__ __forceinline__ ull fmul2(ull a, ull b) {
    ull d;
    asm("mul.rn.f32x2 %0, %1, %2;" : "=l"(d) : "l"(a), "l"(b));
    return d;
}
__device__ __forceinline__ float frcp(float x) {
    float r;
    asm("rcp.approx.f32 %0, %1;" : "=f"(r) : "f"(x));
    return r;
}

// ============================================================================
// Fused kernel. grid = HH*2, block = 256, occ-3.
// Block 2h   (chunk 0): Cauchy bins [0,1024)  -> khat, set flag.
// Block 2h+1 (chunk 1): Cauchy bins [1024,2048) + l=1024 fixup -> khat,
//                        wait flag, fold + radix-4 C2R IFFT + store.
// Consumer waits only on a LOWER block index -> no deadlock.
// ============================================================================
__global__ void __launch_bounds__(NTH, 3)
s4d_fused(const float* __restrict__ lam_re_in, const float* __restrict__ lam_im_in,
          const float* __restrict__ p_re,  const float* __restrict__ p_im,
          const float* __restrict__ b_re,  const float* __restrict__ b_im,
          const float* __restrict__ c_re,  const float* __restrict__ c_im,
          const float* __restrict__ d_in,  const float* __restrict__ log_dt,
          float* __restrict__ out, int write_d)
{
    // Cauchy-phase shared
    __shared__ ulonglong2 cst[NST * 4];
    __shared__ float4 rA[NST];      // raw (lam_re, ur, ui, v)  for l==1024 fixup
    __shared__ float4 rB[NST];      // raw (wr, wi, xr, xi)
    // FFT-phase shared (only used by chunk 1)
    __shared__ float2 Cb[NF];       // FFT ping
    __shared__ float2 Pg[NF];       // FFT pong
    __shared__ float2 tw4[768];     // e^{+2*pi*i*j/1024}

    const int h     = blockIdx.x >> 1;
    const int chunk = blockIdx.x & 1;
    const int tid   = threadIdx.x;
    const int lbase = chunk * LCHUNK;

    // ---- Phase A: per-n invariants ----
    if (tid < NST) {
        const int idx = h * NST + tid;
        float lr = -log1pf(expf(lam_re_in[idx]));   // Lambda_re = -softplus
        float li = lam_im_in[idx];
        float pr = p_re[idx], pi = p_im[idx];
        float br = b_re[idx], bi = b_im[idx];
        float cr = c_re[idx], ci = c_im[idx];
        float ur = pr * br + pi * bi;
        float ui = pr * bi - pi * br;
        float v  = pr * pr + pi * pi;
        float wr = cr * br + ci * bi;
        float wi = cr * bi - ci * br;
        float xr = cr * pr + ci * pi;
        float xi = cr * pi - ci * pr;
        float dr = -lr;                 // g purely imaginary -> dr l-invariant
        cst[tid * 4 + 0] = make_ulonglong2(pack2(ur * dr, ui * dr), pack2(ui, -ur));
        cst[tid * 4 + 1] = make_ulonglong2(pack2(wr * dr, wi * dr), pack2(wi, -wr));
        cst[tid * 4 + 2] = make_ulonglong2(pack2(xr * dr, xi * dr), pack2(xi, -xr));
        cst[tid * 4 + 3] = make_ulonglong2(pack2(v * dr, -v),       pack2(dr * dr, -li));
        rA[tid] = make_float4(lr, ur, ui, v);
        rB[tid] = make_float4(wr, wi, xr, xi);
    }
    const float tdt = 2.0f * expf(-log_dt[h]);    // 2/dt
    __syncthreads();

    // ---- Phase B: Cauchy mainloop (R11-proven: paired f32x2 prep) ----
    float giv[JILP];
#pragma unroll
    for (int j = 0; j < JILP; j++) {
        const int l = lbase + j * NTH + tid;
        float sp, cp;
        sincospif(l * (1.0f / 2048.0f), &sp, &cp);   // theta/2 = pi*l/2048
        giv[j] = tdt * __fdividef(sp, cp);           // g = i * (2/dt) tan(theta/2)
    }
    const ull gi01 = pack2(giv[0], giv[1]);
    const ull gi23 = pack2(giv[2], giv[3]);

    ull aU[JILP], aW[JILP], aX[JILP], aV[JILP];
#pragma unroll
    for (int j = 0; j < JILP; j++)
        aU[j] = aW[j] = aX[j] = aV[j] = 0ull;

#pragma unroll 2
    for (int n = 0; n < NST; n++) {
        const ulonglong2 t0 = cst[4 * n + 0];
        const ulonglong2 t1 = cst[4 * n + 1];
        const ulonglong2 t2 = cst[4 * n + 2];
        const ulonglong2 t3 = cst[4 * n + 3];
        float dr2, nlam;
        unpack2(t3.y, dr2, nlam);                 // (dr^2, -lam)
        const ull nlam2 = pack2(nlam, nlam);
        const ull dr22  = pack2(dr2, dr2);

        // ---- pair A: bins j=0,1 ----
        {
            const ull diA  = fadd2(gi01, nlam2);
            const ull denA = ffma2(diA, diA, dr22);
            float den0, den1, di0, di1;
            unpack2(denA, den0, den1);
            unpack2(diA,  di0,  di1);
            const float s0 = frcp(den0);
            const float s1 = frcp(den1);
            const ull dsA = fmul2(pack2(s0, s1), diA);
            float ds0, ds1;
            unpack2(dsA, ds0, ds1);
            {
                const ull s2  = pack2(s0, s0);
                const ull ds2 = pack2(ds0, ds0);
                const ull q   = pack2(s0, ds0);
                aU[0] = ffma2(t0.x, s2,  aU[0]); aU[0] = ffma2(t0.y, ds2, aU[0]);
                aW[0] = ffma2(t1.x, s2,  aW[0]); aW[0] = ffma2(t1.y, ds2, aW[0]);
                aX[0] = ffma2(t2.x, s2,  aX[0]); aX[0] = ffma2(t2.y, ds2, aX[0]);
                aV[0] = ffma2(t3.x, q,   aV[0]);
            }
            {
                const ull s2  = pack2(s1, s1);
                const ull ds2 = pack2(ds1, ds1);
                const ull q   = pack2(s1, ds1);
                aU[1] = ffma2(t0.x, s2,  aU[1]); aU[1] = ffma2(t0.y, ds2, aU[1]);
                aW[1] = ffma2(t1.x, s2,  aW[1]); aW[1] = ffma2(t1.y, ds2, aW[1]);
                aX[1] = ffma2(t2.x, s2,  aX[1]); aX[1] = ffma2(t2.y, ds2, aX[1]);
                aV[1] = ffma2(t3.x, q,   aV[1]);
            }
        }
        // ---- pair B: bins j=2,3 ----
        {
            const ull diB  = fadd2(gi23, nlam2);
            const ull denB = ffma2(diB, diB, dr22);
            float den2_, den3_, di2_, di3_;
            unpack2(denB, den2_, den3_);
            unpack2(diB,  di2_,  di3_);
            const float s2_ = frcp(den2_);
            const float s3_ = frcp(den3_);
            const ull dsB = fmul2(pack2(s2_, s3_), diB);
            float ds2_, ds3_;
            unpack2(dsB, ds2_, ds3_);
            {
                const ull s2  = pack2(s2_, s2_);
                const ull ds2 = pack2(ds2_, ds2_);
                const ull q   = pack2(s2_, ds2_);
                aU[2] = ffma2(t0.x, s2,  aU[2]); aU[2] = ffma2(t0.y, ds2, aU[2]);
                aW[2] = ffma2(t1.x, s2,  aW[2]); aW[2] = ffma2(t1.y, ds2, aW[2]);
                aX[2] = ffma2(t2.x, s2,  aX[2]); aX[2] = ffma2(t2.y, ds2, aX[2]);
                aV[2] = ffma2(t3.x, q,   aV[2]);
            }
            {
                const ull s2  = pack2(s3_, s3_);
                const ull ds2 = pack2(ds3_, ds3_);
                const ull q   = pack2(s3_, ds3_);
                aU[3] = ffma2(t0.x, s2,  aU[3]); aU[3] = ffma2(t0.y, ds2, aU[3]);
                aW[3] = ffma2(t1.x, s2,  aW[3]); aW[3] = ffma2(t1.y, ds2, aW[3]);
                aX[3] = ffma2(t2.x, s2,  aX[3]); aX[3] = ffma2(t2.y, ds2, aX[3]);
                aV[3] = ffma2(t3.x, q,   aV[3]);
            }
        }
    }

#pragma unroll
    for (int j = 0; j < JILP; j++) {
        float PRBr, PRBi, CRBr, CRBi, CRPr, CRPi, PRPr, PRPi;
        unpack2(aU[j], PRBr, PRBi);
        unpack2(aW[j], CRBr, CRBi);
        unpack2(aX[j], CRPr, CRPi);
        unpack2(aV[j], PRPr, PRPi);
        const float wr_ = 1.0f + PRPr, wi_ = PRPi;
        const float invW = frcp(fmaf(wr_, wr_, wi_ * wi_));
        const float fr = (PRBr * wr_ + PRBi * wi_) * invW;
        const float fi = (PRBi * wr_ - PRBr * wi_) * invW;
        const float er = CRBr - (CRPr * fr - CRPi * fi);
        const float ei = CRBi - (CRPr * fi + CRPi * fr);
        const int l = lbase + j * NTH + tid;
        float sp, cp;
        sincospif(l * (1.0f / 2048.0f), &sp, &cp);
        const float tau = __fdividef(sp, cp);
        // K_hat = (1 + i*tau) * e
        g_khat[h * LFFT + l] = make_float2(er - tau * ei, ei + tau * er);
    }

    // ---- chunk 0: publish and exit ----
    if (chunk == 0) {
        __threadfence();          // make this thread's khat writes visible
        __syncthreads();          // all threads' fences done before flag
        if (tid == 0)
            atomicExch(&g_flag[h], 1u);
        return;
    }

    // ---- chunk 1: l == 1024 fixup (same-thread overwrite of the NaN bin) ----
    if (tid == 0) {
        const float EPS = 1.1920929e-7f;
        const float gr = tdt * (2.0f / EPS);   // g real
        float PRBr = 0.f, PRBi = 0.f, PRPr = 0.f, PRPi = 0.f;
        float CRBr = 0.f, CRBi = 0.f, CRPr = 0.f, CRPi = 0.f;
        for (int n = 0; n < NST; n++) {
            const float4 a = rA[n];
            const float4 b = rB[n];
            float dr2_, nlim;
            unpack2(cst[4 * n + 3].y, dr2_, nlim);   // nlim = -lam
            const float dr = gr - a.x;
            const float di = nlim;
            const float rinv = 1.0f / fmaf(dr, dr, di * di);
            const float Rr =  dr * rinv;
            const float Ri = -di * rinv;
            PRBr = fmaf(a.y, Rr, PRBr); PRBr = fmaf(-a.z, Ri, PRBr);
            PRBi = fmaf(a.y, Ri, PRBi); PRBi = fmaf( a.z, Rr, PRBi);
            PRPr = fmaf(a.w, Rr, PRPr);
            PRPi = fmaf(a.w, Ri, PRPi);
            CRBr = fmaf(b.x, Rr, CRBr); CRBr = fmaf(-b.y, Ri, CRBr);
            CRBi = fmaf(b.x, Ri, CRBi); CRBi = fmaf( b.y, Rr, CRBi);
            CRPr = fmaf(b.z, Rr, CRPr); CRPr = fmaf(-b.w, Ri, CRPr);
            CRPi = fmaf(b.z, Ri, CRPi); CRPi = fmaf( b.w, Rr, CRPi);
        }
        const float wr_ = 1.0f + PRPr, wi_ = PRPi;
        const float invW = 1.0f / fmaf(wr_, wr_, wi_ * wi_);
        const float fr = (PRBr * wr_ + PRBi * wi_) * invW;
        const float fi = (PRBi * wr_ - PRBr * wi_) * invW;
        const float er = CRBr - (CRPr * fr - CRPi * fi);
        const float ei = CRBi - (CRPr * fi + CRPi * fr);
        const float t2 = 2.0f / EPS;
        g_khat[h * LFFT + 1024] = make_float2(t2 * er, t2 * ei);
    }

    // FFT twiddles while waiting is possible; fill them now (independent)
    for (int j = tid; j < 768; j += NTH) {
        float s, c;
        sincospif(j * (1.0f / 512.0f), &s, &c);
        tw4[j] = make_float2(c, s);
    }

    // ---- wait for chunk 0 (lower block index -> guaranteed progress) ----
    if (tid == 0) {
        volatile unsigned int* f = &g_flag[h];
        while (*f == 0u) { __nanosleep(64); }
    }
    __syncthreads();
    __threadfence();   // acquire: order subsequent khat reads after the flag

    // ---- fold directly from gmem (L2-resident) ----
    const float2* __restrict__ Kg = g_khat + h * LFFT;
#pragma unroll
    for (int it = 0; it < NF / NTH; it++) {
        const int k = it * NTH + tid;
        const float2 P  = Kg[k];
        const float2 Qv = Kg[(2048 - k) & 2047];
        const float2 Rv = Kg[1024 - k];
        const float2 Sv = Kg[1024 + k];
        const float Er = (P.x + Qv.x + Rv.x + Sv.x) * 0.25f;
        const float Ei = (P.y - Qv.y - Rv.y + Sv.y) * 0.25f;
        const float Dr = (P.x + Qv.x - Rv.x - Sv.x) * 0.25f;
        const float Di = (P.y - Qv.y + Rv.y - Sv.y) * 0.25f;
        float st, ct;
        sincospif(k * (1.0f / 1024.0f), &st, &ct);
        const float Or = -st * Dr - ct * Di;
        const float Oi =  ct * Dr - st * Di;
        Cb[k] = make_float2(Er + Or, Ei + Oi);
    }

    // ---- 1024-point radix-4 Stockham inverse FFT: 5 stages ----
    {
        float2* Abuf = Cb;
        float2* Bbuf = Pg;
#pragma unroll
        for (int s = 1; s <= 256; s *= 4) {
            __syncthreads();
            const int bi    = tid;
            const int pbase = bi & ~(s - 1);
            const float2 a = Abuf[bi];
            const float2 b = Abuf[bi + 256];
            const float2 c = Abuf[bi + 512];
            const float2 d = Abuf[bi + 768];
            const float t0r = a.x + c.x, t0i = a.y + c.y;
            const float t1r = a.x - c.x, t1i = a.y - c.y;
            const float t2r = b.x + d.x, t2i = b.y + d.y;
            const float t3r = d.y - b.y, t3i = b.x - d.x;   // i*(b-d)
            const int o = bi + 3 * pbase;
            Bbuf[o] = make_float2(t0r + t2r, t0i + t2i);
            const float2 w1 = tw4[pbase];
            const float2 w2 = tw4[2 * pbase];
            const float2 w3 = tw4[3 * pbase];
            const float u1r = t1r + t3r, u1i = t1i + t3i;
            const float u2r = t0r - t2r, u2i = t0i - t2i;
            const float u3r = t1r - t3r, u3i = t1i - t3i;
            Bbuf[o + s]     = make_float2(u1r * w1.x - u1i * w1.y, u1r * w1.y + u1i * w1.x);
            Bbuf[o + 2 * s] = make_float2(u2r * w2.x - u2i * w2.y, u2r * w2.y + u2i * w2.x);
            Bbuf[o + 3 * s] = make_float2(u3r * w3.x - u3i * w3.y, u3r * w3.y + u3i * w3.x);
            float2* tmp = Abuf; Abuf = Bbuf; Bbuf = tmp;
        }
        __syncthreads();
        // 5 swaps: result is in Abuf (== Pg)

        const float sc = 1.0f / (float)NF;
        float2* o2 = (float2*)out;
#pragma unroll
        for (int it = 0; it < NF / NTH; it++) {
            const int n2 = it * NTH + tid;
            const float2 cv = Abuf[n2];
            o2[h * NF + n2] = make_float2(cv.x * sc, cv.y * sc);
        }
    }

    if (write_d && tid == 0)
        out[HH * LFFT + h] = d_in[h];
}

extern "C" void kernel_launch(void* const* d_in, const int* in_sizes, int n_in,
                              void* d_out, int out_size)
{
    const float* lam_re = (const float*)d_in[0];
    const float* lam_im = (const float*)d_in[1];
    const float* p_re   = (const float*)d_in[2];
    const float* p_im   = (const float*)d_in[3];
    const float* b_re   = (const float*)d_in[4];
    const float* b_im   = (const float*)d_in[5];
    const float* c_re   = (const float*)d_in[6];
    const float* c_im   = (const float*)d_in[7];
    const float* Dv     = (const float*)d_in[8];
    const float* log_dt = (const float*)d_in[9];
    float* out = (float*)d_out;

    const int write_d = (out_size >= HH * LFFT + HH) ? 1 : 0;

    // reset producer flags (graph-capturable, deterministic per replay)
    void* flag_ptr = nullptr;
    cudaGetSymbolAddress(&flag_ptr, g_flag);
    cudaMemsetAsync(flag_ptr, 0, HH * sizeof(unsigned int));

    s4d_fused<<<HH * NCHUNK, NTH>>>(lam_re, lam_im, p_re, p_im,
                                    b_re, b_im, c_re, c_im,
                                    Dv, log_dt, out, write_d);
}

// round 17
// speedup vs baseline: 1.1145x; 1.1145x over previous
#include <cuda_runtime.h>

// Problem constants (fixed by the reference: H=512, N=64, CH=1, L=2048)
#define HH   512
#define NST  64
#define LFFT 2048
#define NF   1024      // half-size complex IFFT length
#define NTH  256       // cauchy block size
#define FTH  512       // fft block size (16 warps)
#define LCHUNK 1024    // l-bins per cauchy block
#define NCHUNK (LFFT / LCHUNK)   // 2 blocks per head
#define JILP 4         // l-bins per thread

typedef unsigned long long ull;

// K_hat scratch: 512 heads x 2048 bins x complex64 = 8 MB (static, no allocation)
__device__ float2 g_khat[HH * LFFT];

__device__ __forceinline__ ull pack2(float a, float b) {
    ull r;
    asm("mov.b64 %0, {%1, %2};" : "=l"(r) : "f"(a), "f"(b));
    return r;
}
__device__ __forceinline__ void unpack2(ull v, float& a, float& b) {
    asm("mov.b64 {%0, %1}, %2;" : "=f"(a), "=f"(b) : "l"(v));
}
__device__ __forceinline__ ull ffma2(ull a, ull b, ull c) {
    ull d;
    asm("fma.rn.f32x2 %0, %1, %2, %3;" : "=l"(d) : "l"(a), "l"(b), "l"(c));
    return d;
}
__device__ __forceinline__ ull fadd2(ull a, ull b) {
    ull d;
    asm("add.rn.f32x2 %0, %1, %2;" : "=l"(d) : "l"(a), "l"(b));
    return d;
}
__device__ __forceinline__ ull fmul2(ull a, ull b) {
    ull d;
    asm("mul.rn.f32x2 %0, %1, %2;" : "=l"(d) : "l"(a), "l"(b));
    return d;
}
__device__ __forceinline__ float frcp(float x) {
    float r;
    asm("rcp.approx.f32 %0, %1;" : "=f"(r) : "f"(x));
    return r;
}

// ============================================================================
// Kernel 1 (R11-proven best, 63.5us): Cauchy + Woodbury -> K_hat.
// grid = HH * NCHUNK (1024), block = 256, occ-3, each thread owns 4 bins.
// R6 accumulation (s2/ds2/q splats) + f32x2-paired reciprocal prep.
// ============================================================================
__global__ void __launch_bounds__(NTH, 3)
cauchy_kernel(const float* __restrict__ lam_re_in, const float* __restrict__ lam_im_in,
              const float* __restrict__ p_re,  const float* __restrict__ p_im,
              const float* __restrict__ b_re,  const float* __restrict__ b_im,
              const float* __restrict__ c_re,  const float* __restrict__ c_im,
              const float* __restrict__ log_dt)
{
    // Pre-packed f32x2 operand quads per n (64B):
    //   [0] = { (ur*dr, ui*dr),  (ui, -ur) }    u = conj(P)*B
    //   [1] = { (wr*dr, wi*dr),  (wi, -wr) }    w = conj(C)*B
    //   [2] = { (xr*dr, xi*dr),  (xi, -xr) }    x = conj(C)*P
    //   [3] = { (v*dr, -v),      (dr2, -lam) }  v = |P|^2   (note: MINUS lam)
    __shared__ ulonglong2 cst[NST * 4];
    __shared__ float4 rA[NST];      // raw (lam_re, ur, ui, v)  for l==1024 fixup
    __shared__ float4 rB[NST];      // raw (wr, wi, xr, xi)

    const int h     = blockIdx.x / NCHUNK;
    const int chunk = blockIdx.x % NCHUNK;
    const int tid   = threadIdx.x;
    const int lbase = chunk * LCHUNK;

    if (tid < NST) {
        const int idx = h * NST + tid;
        float lr = -log1pf(expf(lam_re_in[idx]));   // Lambda_re = -softplus
        float li = lam_im_in[idx];
        float pr = p_re[idx], pi = p_im[idx];
        float br = b_re[idx], bi = b_im[idx];
        float cr = c_re[idx], ci = c_im[idx];
        float ur = pr * br + pi * bi;
        float ui = pr * bi - pi * br;
        float v  = pr * pr + pi * pi;
        float wr = cr * br + ci * bi;
        float wi = cr * bi - ci * br;
        float xr = cr * pr + ci * pi;
        float xi = cr * pi - ci * pr;
        float dr = -lr;                 // g purely imaginary -> dr l-invariant
        cst[tid * 4 + 0] = make_ulonglong2(pack2(ur * dr, ui * dr), pack2(ui, -ur));
        cst[tid * 4 + 1] = make_ulonglong2(pack2(wr * dr, wi * dr), pack2(wi, -wr));
        cst[tid * 4 + 2] = make_ulonglong2(pack2(xr * dr, xi * dr), pack2(xi, -xr));
        cst[tid * 4 + 3] = make_ulonglong2(pack2(v * dr, -v),       pack2(dr * dr, -li));
        rA[tid] = make_float4(lr, ur, ui, v);
        rB[tid] = make_float4(wr, wi, xr, xi);
    }
    const float tdt = 2.0f * expf(-log_dt[h]);    // 2/dt
    __syncthreads();

    // gi per bin, packed in j-pairs (tau recomputed in the epilogue)
    float giv[JILP];
#pragma unroll
    for (int j = 0; j < JILP; j++) {
        const int l = lbase + j * NTH + tid;
        float sp, cp;
        sincospif(l * (1.0f / 2048.0f), &sp, &cp);   // theta/2 = pi*l/2048
        giv[j] = tdt * __fdividef(sp, cp);           // g = i * (2/dt) tan(theta/2)
    }
    const ull gi01 = pack2(giv[0], giv[1]);
    const ull gi23 = pack2(giv[2], giv[3]);

    ull aU[JILP], aW[JILP], aX[JILP], aV[JILP];
#pragma unroll
    for (int j = 0; j < JILP; j++)
        aU[j] = aW[j] = aX[j] = aV[j] = 0ull;

#pragma unroll 2
    for (int n = 0; n < NST; n++) {
        const ulonglong2 t0 = cst[4 * n + 0];
        const ulonglong2 t1 = cst[4 * n + 1];
        const ulonglong2 t2 = cst[4 * n + 2];
        const ulonglong2 t3 = cst[4 * n + 3];
        float dr2, nlam;
        unpack2(t3.y, dr2, nlam);                 // (dr^2, -lam)
        const ull nlam2 = pack2(nlam, nlam);
        const ull dr22  = pack2(dr2, dr2);

        // ---- pair A: bins j=0,1 ----
        {
            const ull diA  = fadd2(gi01, nlam2);              // (di0, di1)
            const ull denA = ffma2(diA, diA, dr22);           // (den0, den1)
            float den0, den1, di0, di1;
            unpack2(denA, den0, den1);
            unpack2(diA,  di0,  di1);
            const float s0 = frcp(den0);
            const float s1 = frcp(den1);
            const ull dsA = fmul2(pack2(s0, s1), diA);        // (ds0, ds1)
            float ds0, ds1;
            unpack2(dsA, ds0, ds1);
            {
                const ull s2  = pack2(s0, s0);
                const ull ds2 = pack2(ds0, ds0);
                const ull q   = pack2(s0, ds0);
                aU[0] = ffma2(t0.x, s2,  aU[0]); aU[0] = ffma2(t0.y, ds2, aU[0]);
                aW[0] = ffma2(t1.x, s2,  aW[0]); aW[0] = ffma2(t1.y, ds2, aW[0]);
                aX[0] = ffma2(t2.x, s2,  aX[0]); aX[0] = ffma2(t2.y, ds2, aX[0]);
                aV[0] = ffma2(t3.x, q,   aV[0]);
            }
            {
                const ull s2  = pack2(s1, s1);
                const ull ds2 = pack2(ds1, ds1);
                const ull q   = pack2(s1, ds1);
                aU[1] = ffma2(t0.x, s2,  aU[1]); aU[1] = ffma2(t0.y, ds2, aU[1]);
                aW[1] = ffma2(t1.x, s2,  aW[1]); aW[1] = ffma2(t1.y, ds2, aW[1]);
                aX[1] = ffma2(t2.x, s2,  aX[1]); aX[1] = ffma2(t2.y, ds2, aX[1]);
                aV[1] = ffma2(t3.x, q,   aV[1]);
            }
        }
        // ---- pair B: bins j=2,3 ----
        {
            const ull diB  = fadd2(gi23, nlam2);
            const ull denB = ffma2(diB, diB, dr22);
            float den2_, den3_, di2_, di3_;
            unpack2(denB, den2_, den3_);
            unpack2(diB,  di2_,  di3_);
            const float s2_ = frcp(den2_);
            const float s3_ = frcp(den3_);
            const ull dsB = fmul2(pack2(s2_, s3_), diB);
            float ds2_, ds3_;
            unpack2(dsB, ds2_, ds3_);
            {
                const ull s2  = pack2(s2_, s2_);
                const ull ds2 = pack2(ds2_, ds2_);
                const ull q   = pack2(s2_, ds2_);
                aU[2] = ffma2(t0.x, s2,  aU[2]); aU[2] = ffma2(t0.y, ds2, aU[2]);
                aW[2] = ffma2(t1.x, s2,  aW[2]); aW[2] = ffma2(t1.y, ds2, aW[2]);
                aX[2] = ffma2(t2.x, s2,  aX[2]); aX[2] = ffma2(t2.y, ds2, aX[2]);
                aV[2] = ffma2(t3.x, q,   aV[2]);
            }
            {
                const ull s2  = pack2(s3_, s3_);
                const ull ds2 = pack2(ds3_, ds3_);
                const ull q   = pack2(s3_, ds3_);
                aU[3] = ffma2(t0.x, s2,  aU[3]); aU[3] = ffma2(t0.y, ds2, aU[3]);
                aW[3] = ffma2(t1.x, s2,  aW[3]); aW[3] = ffma2(t1.y, ds2, aW[3]);
                aX[3] = ffma2(t2.x, s2,  aX[3]); aX[3] = ffma2(t2.y, ds2, aX[3]);
                aV[3] = ffma2(t3.x, q,   aV[3]);
            }
        }
    }

#pragma unroll
    for (int j = 0; j < JILP; j++) {
        float PRBr, PRBi, CRBr, CRBi, CRPr, CRPi, PRPr, PRPi;
        unpack2(aU[j], PRBr, PRBi);
        unpack2(aW[j], CRBr, CRBi);
        unpack2(aX[j], CRPr, CRPi);
        unpack2(aV[j], PRPr, PRPi);
        const float wr_ = 1.0f + PRPr, wi_ = PRPi;
        const float invW = frcp(fmaf(wr_, wr_, wi_ * wi_));
        const float fr = (PRBr * wr_ + PRBi * wi_) * invW;
        const float fi = (PRBi * wr_ - PRBr * wi_) * invW;
        const float er = CRBr - (CRPr * fr - CRPi * fi);
        const float ei = CRBi - (CRPr * fi + CRPi * fr);
        const int l = lbase + j * NTH + tid;
        // recompute tau in the epilogue (kept out of mainloop registers)
        float sp, cp;
        sincospif(l * (1.0f / 2048.0f), &sp, &cp);
        const float tau = __fdividef(sp, cp);
        // K_hat = (1 + i*tau) * e
        g_khat[h * LFFT + l] = make_float2(er - tau * ei, ei + tau * er);
    }

    // l == 1024 fixup (z = -1, eps-clamped bin) — chunk 1, tid 0 wrote the NaN
    // bin above (j=0), so this overwrite is same-thread ordered.
    if (chunk == 1 && tid == 0) {
        const float EPS = 1.1920929e-7f;
        const float gr = tdt * (2.0f / EPS);   // g real
        float PRBr = 0.f, PRBi = 0.f, PRPr = 0.f, PRPi = 0.f;
        float CRBr = 0.f, CRBi = 0.f, CRPr = 0.f, CRPi = 0.f;
        for (int n = 0; n < NST; n++) {
            const float4 a = rA[n];
            const float4 b = rB[n];
            float dr2_, nlim;
            unpack2(cst[4 * n + 3].y, dr2_, nlim);   // nlim = -lam
            const float dr = gr - a.x;
            const float di = nlim;                   // -lam
            const float rinv = 1.0f / fmaf(dr, dr, di * di);
            const float Rr =  dr * rinv;
            const float Ri = -di * rinv;
            PRBr = fmaf(a.y, Rr, PRBr); PRBr = fmaf(-a.z, Ri, PRBr);
            PRBi = fmaf(a.y, Ri, PRBi); PRBi = fmaf( a.z, Rr, PRBi);
            PRPr = fmaf(a.w, Rr, PRPr);
            PRPi = fmaf(a.w, Ri, PRPi);
            CRBr = fmaf(b.x, Rr, CRBr); CRBr = fmaf(-b.y, Ri, CRBr);
            CRBi = fmaf(b.x, Ri, CRBi); CRBi = fmaf( b.y, Rr, CRBi);
            CRPr = fmaf(b.z, Rr, CRPr); CRPr = fmaf(-b.w, Ri, CRPr);
            CRPi = fmaf(b.z, Ri, CRPi); CRPi = fmaf( b.w, Rr, CRPi);
        }
        const float wr_ = 1.0f + PRPr, wi_ = PRPi;
        const float invW = 1.0f / fmaf(wr_, wr_, wi_ * wi_);
        const float fr = (PRBr * wr_ + PRBi * wi_) * invW;
        const float fi = (PRBi * wr_ - PRBr * wi_) * invW;
        const float er = CRBr - (CRPr * fr - CRPi * fi);
        const float ei = CRBi - (CRPr * fi + CRPi * fr);
        const float t2 = 2.0f / EPS;
        g_khat[h * LFFT + 1024] = make_float2(t2 * er, t2 * ei);
    }
}

// ============================================================================
// Kernel 2 (R14-proven best, 8.86us): Hermitian fold (direct from L2-resident
// gmem) + radix-4 C2R IFFT. FTH=512; butterflies on threads < 256.
// ============================================================================
__global__ void __launch_bounds__(FTH)
fft_kernel(const float* __restrict__ d_in, float* __restrict__ out, int write_d)
{
    __shared__ float2 Cb[NF];       // FFT ping
    __shared__ float2 Pg[NF];       // FFT pong
    __shared__ float2 tw4[768];     // e^{+2*pi*i*j/1024}, j < 768

    const int h   = blockIdx.x;
    const int tid = threadIdx.x;

    // twiddles (768 entries, all threads participate)
    {
        float s, c;
        sincospif(tid * (1.0f / 512.0f), &s, &c);
        tw4[tid] = make_float2(c, s);
        if (tid < 256) {
            float s2, c2;
            sincospif((tid + 512) * (1.0f / 512.0f), &s2, &c2);
            tw4[tid + 512] = make_float2(c2, s2);
        }
    }

    // Fold directly from gmem (g_khat is L2-resident, written by cauchy):
    // Re(ifft2048(X)) == ifft1024(C) interleaved as (x[2n], x[2n+1])
    const float2* __restrict__ Kg = g_khat + h * LFFT;
#pragma unroll
    for (int it = 0; it < NF / FTH; it++) {
        const int k = it * FTH + tid;
        const float2 P  = Kg[k];
        const float2 Qv = Kg[(2048 - k) & 2047];
        const float2 Rv = Kg[1024 - k];
        const float2 Sv = Kg[1024 + k];
        const float Er = (P.x + Qv.x + Rv.x + Sv.x) * 0.25f;
        const float Ei = (P.y - Qv.y - Rv.y + Sv.y) * 0.25f;
        const float Dr = (P.x + Qv.x - Rv.x - Sv.x) * 0.25f;
        const float Di = (P.y - Qv.y + Rv.y - Sv.y) * 0.25f;
        float st, ct;
        sincospif(k * (1.0f / 1024.0f), &st, &ct);
        const float Or = -st * Dr - ct * Di;
        const float Oi =  ct * Dr - st * Di;
        Cb[k] = make_float2(Er + Or, Ei + Oi);
    }

    // 1024-point radix-4 Stockham inverse FFT: 5 stages, threads < 256 butterfly
    {
        float2* Abuf = Cb;
        float2* Bbuf = Pg;
#pragma unroll
        for (int s = 1; s <= 256; s *= 4) {
            __syncthreads();
            if (tid < 256) {
                const int bi    = tid;
                const int pbase = bi & ~(s - 1);
                const float2 a = Abuf[bi];
                const float2 b = Abuf[bi + 256];
                const float2 c = Abuf[bi + 512];
                const float2 d = Abuf[bi + 768];
                const float t0r = a.x + c.x, t0i = a.y + c.y;
                const float t1r = a.x - c.x, t1i = a.y - c.y;
                const float t2r = b.x + d.x, t2i = b.y + d.y;
                const float t3r = d.y - b.y, t3i = b.x - d.x;   // i*(b-d)
                const int o = bi + 3 * pbase;
                Bbuf[o] = make_float2(t0r + t2r, t0i + t2i);
                const float2 w1 = tw4[pbase];
                const float2 w2 = tw4[2 * pbase];
                const float2 w3 = tw4[3 * pbase];
                const float u1r = t1r + t3r, u1i = t1i + t3i;
                const float u2r = t0r - t2r, u2i = t0i - t2i;
                const float u3r = t1r - t3r, u3i = t1i - t3i;
                Bbuf[o + s]     = make_float2(u1r * w1.x - u1i * w1.y, u1r * w1.y + u1i * w1.x);
                Bbuf[o + 2 * s] = make_float2(u2r * w2.x - u2i * w2.y, u2r * w2.y + u2i * w2.x);
                Bbuf[o + 3 * s] = make_float2(u3r * w3.x - u3i * w3.y, u3r * w3.y + u3i * w3.x);
            }
            float2* tmp = Abuf; Abuf = Bbuf; Bbuf = tmp;
        }
        __syncthreads();
        // 5 swaps: result is in Abuf (== Pg)

        // c[n] -> (x[2n], x[2n+1]) with 1/1024 scale; all 512 threads store
        const float sc = 1.0f / (float)NF;
        float2* o2 = (float2*)out;
#pragma unroll
        for (int it = 0; it < NF / FTH; it++) {
            const int n2 = it * FTH + tid;
            const float2 cv = Abuf[n2];
            o2[h * NF + n2] = make_float2(cv.x * sc, cv.y * sc);
        }
    }

    if (write_d && tid == 0)
        out[HH * LFFT + h] = d_in[h];
}

extern "C" void kernel_launch(void* const* d_in, const int* in_sizes, int n_in,
                              void* d_out, int out_size)
{
    const float* lam_re = (const float*)d_in[0];
    const float* lam_im = (const float*)d_in[1];
    const float* p_re   = (const float*)d_in[2];
    const float* p_im   = (const float*)d_in[3];
    const float* b_re   = (const float*)d_in[4];
    const float* b_im   = (const float*)d_in[5];
    const float* c_re   = (const float*)d_in[6];
    const float* c_im   = (const float*)d_in[7];
    const float* Dv     = (const float*)d_in[8];
    const float* log_dt = (const float*)d_in[9];
    float* out = (float*)d_out;

    const int write_d = (out_size >= HH * LFFT + HH) ? 1 : 0;

    cauchy_kernel<<<HH * NCHUNK, NTH>>>(lam_re, lam_im, p_re, p_im,
                                        b_re, b_im, c_re, c_im, log_dt);
    fft_kernel<<<HH, FTH>>>(Dv, out, write_d);
}